// round 3
// baseline (speedup 1.0000x reference)
#include <cuda_runtime.h>

// Problem constants
#define Bc   4
#define Vc   5
#define Jc   15
#define Hc   128
#define Wc   240
#define NPTS 128000      // 80*80*20
#define JP   16          // J padded to 16 floats (64B per pixel)

// Transposed heatmaps: (B*V, H, W, JP) float = 39.3 MB scratch
__device__ float g_hmT[(size_t)Bc * Vc * Hc * Wc * JP];

// ---------------------------------------------------------------------------
// Kernel 1: transpose (B,V,J,H,W) -> (B*V, H, W, JP) with JP=16 zero-padded.
// One block per (bv, y) row. Coalesced reads per joint-row into smem, then
// coalesced float4 writes of the interleaved output row.
// ---------------------------------------------------------------------------
__global__ void __launch_bounds__(256) transpose_kernel(const float* __restrict__ hm) {
    const int bv = blockIdx.x;   // 0..19
    const int y  = blockIdx.y;   // 0..127

    __shared__ float s[Jc][Wc];  // 14.4 KB

    const float* src = hm + ((size_t)bv * Jc) * (Hc * Wc) + (size_t)y * Wc;
#pragma unroll
    for (int j = 0; j < Jc; ++j) {
        for (int x = threadIdx.x; x < Wc; x += blockDim.x)
            s[j][x] = src[(size_t)j * (Hc * Wc) + x];
    }
    __syncthreads();

    float4* dst = reinterpret_cast<float4*>(
        g_hmT + ((size_t)bv * Hc * Wc + (size_t)y * Wc) * JP);

    const int total = Wc * JP / 4;  // 960 float4 per row
    for (int f = threadIdx.x; f < total; f += blockDim.x) {
        int x = f >> 2;
        int g = (f & 3) * 4;
        float4 v4;
        v4.x = s[g + 0][x];
        v4.y = s[g + 1][x];
        v4.z = s[g + 2][x];
        v4.w = (g + 3 < Jc) ? s[g + 3][x] : 0.0f;
        dst[f] = v4;
    }
}

// ---------------------------------------------------------------------------
// Kernel 2: gather. One thread per (b, n). Loops over the 5 views,
// bilinear-samples all 15 joints with 16x LDG.128 per view, accumulates in
// registers, then mean + clip + coalesced stores.
// ---------------------------------------------------------------------------
__global__ void __launch_bounds__(256) sample_kernel(const float* __restrict__ grid,
                                                     float* __restrict__ out) {
    const int tid = blockIdx.x * blockDim.x + threadIdx.x;
    if (tid >= Bc * NPTS) return;
    const int b = tid / NPTS;
    const int n = tid - b * NPTS;

    float4 a0 = make_float4(0.f, 0.f, 0.f, 0.f);
    float4 a1 = a0, a2 = a0, a3 = a0;

    const float2* g2 = reinterpret_cast<const float2*>(grid);

#pragma unroll
    for (int v = 0; v < Vc; ++v) {
        const float2 g = g2[(size_t)(b * Vc + v) * NPTS + n];
        const float ix = (g.x + 1.0f) * 0.5f * (float)(Wc - 1);
        const float iy = (g.y + 1.0f) * 0.5f * (float)(Hc - 1);
        const float x0f = floorf(ix);
        const float y0f = floorf(iy);
        const float wx1 = ix - x0f;
        const float wy1 = iy - y0f;
        const float wx0 = 1.0f - wx1;
        const float wy0 = 1.0f - wy1;

        int x0 = (int)x0f;
        int y0 = (int)y0f;
        x0 = max(0, min(x0, Wc - 1));
        y0 = max(0, min(y0, Hc - 1));
        const int x1 = min(x0 + 1, Wc - 1);
        const int y1 = min(y0 + 1, Hc - 1);

        const float w00 = wx0 * wy0;
        const float w10 = wx1 * wy0;
        const float w01 = wx0 * wy1;
        const float w11 = wx1 * wy1;

        const float4* base = reinterpret_cast<const float4*>(g_hmT)
                           + (size_t)(b * Vc + v) * (Hc * Wc) * (JP / 4);

        const float4* p00 = base + ((size_t)y0 * Wc + x0) * (JP / 4);
        const float4* p10 = base + ((size_t)y0 * Wc + x1) * (JP / 4);
        const float4* p01 = base + ((size_t)y1 * Wc + x0) * (JP / 4);
        const float4* p11 = base + ((size_t)y1 * Wc + x1) * (JP / 4);

#define FMA4_CORNER(P, WT)                                                   \
        {                                                                    \
            const float4 q0 = (P)[0], q1 = (P)[1], q2 = (P)[2], q3 = (P)[3]; \
            a0.x += (WT) * q0.x; a0.y += (WT) * q0.y;                        \
            a0.z += (WT) * q0.z; a0.w += (WT) * q0.w;                        \
            a1.x += (WT) * q1.x; a1.y += (WT) * q1.y;                        \
            a1.z += (WT) * q1.z; a1.w += (WT) * q1.w;                        \
            a2.x += (WT) * q2.x; a2.y += (WT) * q2.y;                        \
            a2.z += (WT) * q2.z; a2.w += (WT) * q2.w;                        \
            a3.x += (WT) * q3.x; a3.y += (WT) * q3.y;                        \
            a3.z += (WT) * q3.z; a3.w += (WT) * q3.w;                        \
        }

        FMA4_CORNER(p00, w00)
        FMA4_CORNER(p10, w10)
        FMA4_CORNER(p01, w01)
        FMA4_CORNER(p11, w11)
#undef FMA4_CORNER
    }

    const float s = 1.0f / (float)Vc;
    float r[16];
    r[0]  = a0.x; r[1]  = a0.y; r[2]  = a0.z; r[3]  = a0.w;
    r[4]  = a1.x; r[5]  = a1.y; r[6]  = a1.z; r[7]  = a1.w;
    r[8]  = a2.x; r[9]  = a2.y; r[10] = a2.z; r[11] = a2.w;
    r[12] = a3.x; r[13] = a3.y; r[14] = a3.z;

    float* op = out + (size_t)b * Jc * NPTS + n;
#pragma unroll
    for (int j = 0; j < Jc; ++j) {
        float val = r[j] * s;
        val = fminf(fmaxf(val, 0.0f), 1.0f);
        op[(size_t)j * NPTS] = val;
    }
}

// ---------------------------------------------------------------------------
extern "C" void kernel_launch(void* const* d_in, const int* in_sizes, int n_in,
                              void* d_out, int out_size) {
    const float* heatmaps = (const float*)d_in[0];  // (4,5,15,128,240) f32
    const float* grid     = (const float*)d_in[1];  // (4,5,1,128000,2) f32
    float* out            = (float*)d_out;          // (4,15,80,80,20) f32

    (void)in_sizes; (void)n_in; (void)out_size;

    dim3 tgrid(Bc * Vc, Hc);
    transpose_kernel<<<tgrid, 256>>>(heatmaps);

    const int total = Bc * NPTS;  // 512000
    sample_kernel<<<(total + 255) / 256, 256>>>(grid, out);
}

// round 5
// speedup vs baseline: 2.0651x; 2.0651x over previous
#include <cuda_runtime.h>
#include <cuda_fp16.h>

// Problem constants
#define Bc   4
#define Vc   5
#define Jc   15
#define Hc   128
#define Wc   240
#define NPTS 128000      // 80*80*20
#define JP   16          // J padded to 16 halves (32B per pixel)

// One pixel = 16 fp16 joints = 32 bytes, 32B-aligned for LDG.256
struct alignas(32) Pix { uint4 a, b; };

// Transposed fp16 heatmaps: (B*V, H, W) pixels of 16 halves = 19.66 MB
__device__ Pix g_hmT[(size_t)Bc * Vc * Hc * Wc];

static __device__ __forceinline__ unsigned pack_h2(float lo, float hi) {
    __half2 h = __floats2half2_rn(lo, hi);
    return *reinterpret_cast<unsigned*>(&h);
}

// ---------------------------------------------------------------------------
// Kernel 1: transpose (B,V,J,H,W) f32 -> (B*V, H, W, 16) f16, zero-padded.
// One block per (bv, y) row; coalesced reads into smem, packed uint4 writes.
// ---------------------------------------------------------------------------
__global__ void __launch_bounds__(256) transpose_kernel(const float* __restrict__ hm) {
    const int bv = blockIdx.x;   // 0..19
    const int y  = blockIdx.y;   // 0..127

    __shared__ float s[Jc][Wc];  // 14.4 KB

    const float* src = hm + ((size_t)bv * Jc) * (Hc * Wc) + (size_t)y * Wc;
#pragma unroll
    for (int j = 0; j < Jc; ++j) {
        for (int x = threadIdx.x; x < Wc; x += blockDim.x)
            s[j][x] = src[(size_t)j * (Hc * Wc) + x];
    }
    __syncthreads();

    uint4* dst = reinterpret_cast<uint4*>(g_hmT + ((size_t)bv * Hc + y) * Wc);

    const int total = Wc * 2;            // 480 uint4 per row (2 per pixel)
    for (int f = threadIdx.x; f < total; f += blockDim.x) {
        const int x = f >> 1;
        const int g = (f & 1) * 8;       // joint base 0 or 8
        uint4 v;
        v.x = pack_h2(s[g + 0][x], s[g + 1][x]);
        v.y = pack_h2(s[g + 2][x], s[g + 3][x]);
        v.z = pack_h2(s[g + 4][x], s[g + 5][x]);
        v.w = pack_h2(s[g + 6][x],
                      (g + 7 < Jc) ? s[g + 7][x] : 0.0f);
        dst[f] = v;
    }
}

// ---------------------------------------------------------------------------
// 256-bit read-only global load (Blackwell LDG.E.256): one full pixel.
// ---------------------------------------------------------------------------
static __device__ __forceinline__ void ldg256(const Pix* p, float (&f)[8]) {
    asm volatile(
        "ld.global.nc.v8.f32 {%0,%1,%2,%3,%4,%5,%6,%7}, [%8];"
        : "=f"(f[0]), "=f"(f[1]), "=f"(f[2]), "=f"(f[3]),
          "=f"(f[4]), "=f"(f[5]), "=f"(f[6]), "=f"(f[7])
        : "l"(p));
}

static __device__ __forceinline__ void acc_corner(float (&acc)[16],
                                                  const float (&f)[8], float w) {
#pragma unroll
    for (int i = 0; i < 8; ++i) {
        __half2 h = *reinterpret_cast<const __half2*>(&f[i]);
        float2 u = __half22float2(h);
        acc[2 * i + 0] = fmaf(w, u.x, acc[2 * i + 0]);
        acc[2 * i + 1] = fmaf(w, u.y, acc[2 * i + 1]);
    }
}

// ---------------------------------------------------------------------------
// Kernel 2: gather. One thread per (b, n). Per view: 4 corners, one LDG.256
// each; fp32 accumulate; mean + clip; coalesced stores.
// ---------------------------------------------------------------------------
__global__ void __launch_bounds__(256) sample_kernel(const float* __restrict__ grid,
                                                     float* __restrict__ out) {
    const int tid = blockIdx.x * blockDim.x + threadIdx.x;
    if (tid >= Bc * NPTS) return;
    const int b = tid / NPTS;
    const int n = tid - b * NPTS;

    float acc[16];
#pragma unroll
    for (int i = 0; i < 16; ++i) acc[i] = 0.0f;

    const float2* g2 = reinterpret_cast<const float2*>(grid);

#pragma unroll
    for (int v = 0; v < Vc; ++v) {
        const float2 g = g2[(size_t)(b * Vc + v) * NPTS + n];
        const float ix = (g.x + 1.0f) * 0.5f * (float)(Wc - 1);
        const float iy = (g.y + 1.0f) * 0.5f * (float)(Hc - 1);
        const float x0f = floorf(ix);
        const float y0f = floorf(iy);
        const float wx1 = ix - x0f;
        const float wy1 = iy - y0f;
        const float wx0 = 1.0f - wx1;
        const float wy0 = 1.0f - wy1;

        int x0 = (int)x0f;
        int y0 = (int)y0f;
        x0 = max(0, min(x0, Wc - 1));
        y0 = max(0, min(y0, Hc - 1));
        const int x1 = min(x0 + 1, Wc - 1);
        const int y1 = min(y0 + 1, Hc - 1);

        const Pix* base = g_hmT + (size_t)(b * Vc + v) * (Hc * Wc);
        const Pix* r0 = base + (size_t)y0 * Wc;
        const Pix* r1 = base + (size_t)y1 * Wc;

        float f00[8], f10[8], f01[8], f11[8];
        ldg256(r0 + x0, f00);
        ldg256(r0 + x1, f10);
        ldg256(r1 + x0, f01);
        ldg256(r1 + x1, f11);

        acc_corner(acc, f00, wx0 * wy0);
        acc_corner(acc, f10, wx1 * wy0);
        acc_corner(acc, f01, wx0 * wy1);
        acc_corner(acc, f11, wx1 * wy1);
    }

    const float s = 1.0f / (float)Vc;
    float* op = out + (size_t)b * Jc * NPTS + n;
#pragma unroll
    for (int j = 0; j < Jc; ++j) {
        float val = acc[j] * s;
        val = fminf(fmaxf(val, 0.0f), 1.0f);
        op[(size_t)j * NPTS] = val;
    }
}

// ---------------------------------------------------------------------------
extern "C" void kernel_launch(void* const* d_in, const int* in_sizes, int n_in,
                              void* d_out, int out_size) {
    const float* heatmaps = (const float*)d_in[0];  // (4,5,15,128,240) f32
    const float* grid     = (const float*)d_in[1];  // (4,5,1,128000,2) f32
    float* out            = (float*)d_out;          // (4,15,80,80,20) f32

    (void)in_sizes; (void)n_in; (void)out_size;

    dim3 tgrid(Bc * Vc, Hc);
    transpose_kernel<<<tgrid, 256>>>(heatmaps);

    const int total = Bc * NPTS;  // 512000
    sample_kernel<<<(total + 255) / 256, 256>>>(grid, out);
}

// round 6
// speedup vs baseline: 3.2206x; 1.5595x over previous
#include <cuda_runtime.h>
#include <cuda_fp16.h>

// Problem constants
#define Bc   4
#define Vc   5
#define Jc   15
#define Hc   128
#define Wc   240
#define NPTS 128000      // 80*80*20
#define HW   (Hc * Wc)

// One pixel = 16 fp16 joints = 32 bytes, 32B-aligned for LDG.256
struct alignas(32) Pix { uint4 a, b; };

// Transposed fp16 heatmaps: (B*V, H, W) pixels of 16 halves = 19.66 MB
__device__ Pix g_hmT[(size_t)Bc * Vc * HW];

static __device__ __forceinline__ unsigned pack_h2(float lo, float hi) {
    __half2 h = __floats2half2_rn(lo, hi);
    return *reinterpret_cast<unsigned*>(&h);
}

// ---------------------------------------------------------------------------
// Kernel 1: transpose (B,V,J,H,W) f32 -> (B*V, H*W) pixels of 16 f16.
// One thread per pixel: 15 coalesced strided loads, register pack,
// 2 coalesced 128-bit stores. No smem, no syncthreads, no bank conflicts.
// ---------------------------------------------------------------------------
__global__ void __launch_bounds__(256) transpose_kernel(const float* __restrict__ hm) {
    const int idx = blockIdx.x * blockDim.x + threadIdx.x;
    if (idx >= Bc * Vc * HW) return;
    const int bv  = idx / HW;
    const int pix = idx - bv * HW;

    const float* src = hm + (size_t)bv * Jc * HW + pix;
    float v[16];
#pragma unroll
    for (int j = 0; j < Jc; ++j)
        v[j] = __ldg(src + (size_t)j * HW);
    v[15] = 0.0f;

    Pix p;
    p.a.x = pack_h2(v[0],  v[1]);
    p.a.y = pack_h2(v[2],  v[3]);
    p.a.z = pack_h2(v[4],  v[5]);
    p.a.w = pack_h2(v[6],  v[7]);
    p.b.x = pack_h2(v[8],  v[9]);
    p.b.y = pack_h2(v[10], v[11]);
    p.b.z = pack_h2(v[12], v[13]);
    p.b.w = pack_h2(v[14], v[15]);
    g_hmT[idx] = p;
}

// ---------------------------------------------------------------------------
// 256-bit read-only global load (Blackwell LDG.E.256): one full pixel.
// ---------------------------------------------------------------------------
static __device__ __forceinline__ void ldg256(const Pix* p, float (&f)[8]) {
    asm volatile(
        "ld.global.nc.v8.f32 {%0,%1,%2,%3,%4,%5,%6,%7}, [%8];"
        : "=f"(f[0]), "=f"(f[1]), "=f"(f[2]), "=f"(f[3]),
          "=f"(f[4]), "=f"(f[5]), "=f"(f[6]), "=f"(f[7])
        : "l"(p));
}

static __device__ __forceinline__ void acc_corner(float (&acc)[16],
                                                  const float (&f)[8], float w) {
#pragma unroll
    for (int i = 0; i < 8; ++i) {
        __half2 h = *reinterpret_cast<const __half2*>(&f[i]);
        float2 u = __half22float2(h);
        acc[2 * i + 0] = fmaf(w, u.x, acc[2 * i + 0]);
        acc[2 * i + 1] = fmaf(w, u.y, acc[2 * i + 1]);
    }
}

// ---------------------------------------------------------------------------
// Kernel 2: gather, lane-paired. TWO threads per (b, n): lane j in {0,1}
// handles column x0+j. The two lanes' 32B pixel loads are contiguous 64B,
// so they coalesce into shared L1 wavefronts within one LDG instruction
// (x0/x1 pixels share a 128B line with p=3/4). Partner sums combine via
// shfl_xor(1); lane0 stores joints 0-7, lane1 stores 8-14.
// ---------------------------------------------------------------------------
__global__ void __launch_bounds__(256) sample_kernel(const float* __restrict__ grid,
                                                     float* __restrict__ out) {
    const int tid = blockIdx.x * blockDim.x + threadIdx.x;  // 0 .. 2*B*NPTS-1
    const int pid = tid >> 1;        // point id
    const int jl  = tid & 1;         // lane role: 0 -> x0 column, 1 -> x1 column
    const int b   = pid / NPTS;
    const int n   = pid - b * NPTS;

    float acc[16];
#pragma unroll
    for (int i = 0; i < 16; ++i) acc[i] = 0.0f;

    const float2* g2 = reinterpret_cast<const float2*>(grid);

#pragma unroll
    for (int v = 0; v < Vc; ++v) {
        const float2 g = g2[(size_t)(b * Vc + v) * NPTS + n];
        const float ix = (g.x + 1.0f) * 0.5f * (float)(Wc - 1);
        const float iy = (g.y + 1.0f) * 0.5f * (float)(Hc - 1);
        const float x0f = floorf(ix);
        const float y0f = floorf(iy);
        const float wx1 = ix - x0f;
        const float wy1 = iy - y0f;

        int x0 = (int)x0f;
        int y0 = (int)y0f;
        x0 = max(0, min(x0, Wc - 1));
        y0 = max(0, min(y0, Hc - 1));
        const int xc = min(x0 + jl, Wc - 1);   // this lane's column
        const int y1 = min(y0 + 1, Hc - 1);

        // this lane's x-weight (weight is 0 whenever the clamp engaged)
        const float wx = jl ? wx1 : (1.0f - wx1);
        const float w0 = wx * (1.0f - wy1);
        const float w1 = wx * wy1;

        const Pix* base = g_hmT + (size_t)(b * Vc + v) * HW;

        float f0[8], f1[8];
        ldg256(base + (size_t)y0 * Wc + xc, f0);
        ldg256(base + (size_t)y1 * Wc + xc, f1);

        acc_corner(acc, f0, w0);
        acc_corner(acc, f1, w1);
    }

    // Combine partner lanes: both end up with the full 2-corner-pair sum.
#pragma unroll
    for (int i = 0; i < 15; ++i)
        acc[i] += __shfl_xor_sync(0xffffffffu, acc[i], 1);

    const float s = 1.0f / (float)Vc;
    float* op = out + (size_t)b * Jc * NPTS + n;

    if (jl == 0) {
#pragma unroll
        for (int j = 0; j < 8; ++j) {
            float val = acc[j] * s;
            val = fminf(fmaxf(val, 0.0f), 1.0f);
            op[(size_t)j * NPTS] = val;
        }
    } else {
#pragma unroll
        for (int j = 8; j < Jc; ++j) {
            float val = acc[j] * s;
            val = fminf(fmaxf(val, 0.0f), 1.0f);
            op[(size_t)j * NPTS] = val;
        }
    }
}

// ---------------------------------------------------------------------------
extern "C" void kernel_launch(void* const* d_in, const int* in_sizes, int n_in,
                              void* d_out, int out_size) {
    const float* heatmaps = (const float*)d_in[0];  // (4,5,15,128,240) f32
    const float* grid     = (const float*)d_in[1];  // (4,5,1,128000,2) f32
    float* out            = (float*)d_out;          // (4,15,80,80,20) f32

    (void)in_sizes; (void)n_in; (void)out_size;

    const int tp_total = Bc * Vc * HW;              // 614400
    transpose_kernel<<<(tp_total + 255) / 256, 256>>>(heatmaps);

    const int total = Bc * NPTS * 2;                // 1,024,000
    sample_kernel<<<(total + 255) / 256, 256>>>(grid, out);
}